// round 14
// baseline (speedup 1.0000x reference)
#include <cuda_runtime.h>

// Problem constants
#define B_  2
#define N_  2048
#define D_  1024
#define H_  16
#define DH_ 64
#define DI_ 1024
#define LOG2E_ 1.4426950408889634f
#define QSCALE_ (0.125f * LOG2E_)   // attention scale * log2e (base-2 softmax)

// Scratch (device globals: allocation-free per harness rules)
__device__ float g_q[B_*H_*N_*DH_];      // [b,h,n,d] tf32-exact, *QSCALE folded
__device__ float g_k[B_*H_*N_*DH_];      // [b,h,n,d] tf32-exact
__device__ float g_v[B_*H_*DH_*N_];      // [b,h,d,n] TRANSPOSED, tf32-exact
__device__ float g_att[B_*N_*DI_];       // full f32
__device__ float g_gated[B_*N_*DI_];     // gate GEMM raw acc, then gated tf32
// tf32-rounded inputs (prepass); weights stored TRANSPOSED [out][in]
__device__ float g_seq[B_*N_*D_];
__device__ float g_wqkv[3*DI_*D_];       // row n: n<1024 Wq^T, else Wkv^T
__device__ float g_wg [DI_*D_];
__device__ float g_wo [D_*DI_];

// ---------------------------------------------------------------------------
// helpers
// ---------------------------------------------------------------------------
__device__ __forceinline__ unsigned f2tf(float x) {
    unsigned r;
    asm("cvt.rna.tf32.f32 %0, %1;" : "=r"(r) : "f"(x));
    return r;
}
__device__ __forceinline__ float f2tff(float x) {
    return __uint_as_float(f2tf(x));
}
__device__ __forceinline__ float ex2f(float x) {
    float y;
    asm("ex2.approx.f32 %0, %1;" : "=f"(y) : "f"(x));
    return y;
}

__device__ __forceinline__ void mma8(float* c, const unsigned* a, const unsigned* b) {
    asm volatile(
        "mma.sync.aligned.m16n8k8.row.col.f32.tf32.tf32.f32 "
        "{%0,%1,%2,%3},{%4,%5,%6,%7},{%8,%9},{%0,%1,%2,%3};"
        : "+f"(c[0]), "+f"(c[1]), "+f"(c[2]), "+f"(c[3])
        : "r"(a[0]), "r"(a[1]), "r"(a[2]), "r"(a[3]), "r"(b[0]), "r"(b[1]));
}

__device__ __forceinline__ unsigned sptr(const void* p) {
    return (unsigned)__cvta_generic_to_shared(p);
}
#define CP16(dst, src) \
    asm volatile("cp.async.cg.shared.global [%0], [%1], 16;" :: "r"(dst), "l"(src))
#define CP_COMMIT() asm volatile("cp.async.commit_group;" ::: "memory")
#define CP_WAIT(n)  asm volatile("cp.async.wait_group %0;" :: "n"(n) : "memory")
#define LDSM4(r0, r1, r2, r3, addr) \
    asm volatile("ldmatrix.sync.aligned.m8n8.x4.shared.b16 {%0,%1,%2,%3}, [%4];" \
        : "=r"(r0), "=r"(r1), "=r"(r2), "=r"(r3) : "r"(addr))
#define PAIR_BAR(id) \
    asm volatile("bar.sync %0, 64;" :: "r"(id) : "memory")

// ---------------------------------------------------------------------------
// Prepass A: round seq to tf32-exact
// ---------------------------------------------------------------------------
__global__ void prep_seq_kernel(const float4* __restrict__ seq)
{
    const int i = blockIdx.x * blockDim.x + threadIdx.x;
    if (i >= B_*N_*D_/4) return;
    float4 v = seq[i];
    v.x = f2tff(v.x); v.y = f2tff(v.y); v.z = f2tff(v.z); v.w = f2tff(v.w);
    ((float4*)g_seq)[i] = v;
}

// ---------------------------------------------------------------------------
// Prepass B: transpose + round weights. In [1024][W] -> out [W][1024].
// ---------------------------------------------------------------------------
__global__ void prep_wT_kernel(const float* __restrict__ wq,
                               const float* __restrict__ wkv,
                               const float* __restrict__ wg,
                               const float* __restrict__ wo)
{
    __shared__ float t[32][33];
    int tt = blockIdx.x;
    const float* src;
    float* dst;
    int W, kt, nt, noff;
    if (tt < 1024)      { src = wq;  dst = g_wqkv; W = 1024; nt = tt & 31; kt = tt >> 5; noff = 0; }
    else if (tt < 3072) { tt -= 1024; src = wkv; dst = g_wqkv; W = 2048; nt = tt & 63; kt = tt >> 6; noff = 1024; }
    else if (tt < 4096) { tt -= 3072; src = wg;  dst = g_wg;  W = 1024; nt = tt & 31; kt = tt >> 5; noff = 0; }
    else                { tt -= 4096; src = wo;  dst = g_wo;  W = 1024; nt = tt & 31; kt = tt >> 5; noff = 0; }
    const int tx = threadIdx.x & 31, ty = threadIdx.x >> 5;
    #pragma unroll
    for (int i = 0; i < 4; i++)
        t[ty + 8*i][tx] = f2tff(src[(size_t)(kt*32 + ty + 8*i) * W + nt*32 + tx]);
    __syncthreads();
    #pragma unroll
    for (int i = 0; i < 4; i++)
        dst[(size_t)(noff + nt*32 + ty + 8*i) * 1024 + kt*32 + tx] = t[tx][ty + 8*i];
}

// ---------------------------------------------------------------------------
// Gating: g_gated = round_tf32(g_att * sigmoid(g_gated + bg))  (in-place)
// ---------------------------------------------------------------------------
__global__ void gating_kernel(const float* __restrict__ bg)
{
    const int i = blockIdx.x * blockDim.x + threadIdx.x;
    if (i >= B_*N_*DI_/4) return;
    float4 a = ((const float4*)g_att)[i];
    float4 g = ((float4*)g_gated)[i];
    const int c = (i * 4) & (DI_ - 1);
    float4 bb = *(const float4*)&bg[c];
    g.x = f2tff(a.x / (1.f + __expf(-(g.x + bb.x))));
    g.y = f2tff(a.y / (1.f + __expf(-(g.y + bb.y))));
    g.z = f2tff(a.z / (1.f + __expf(-(g.z + bb.z))));
    g.w = f2tff(a.w / (1.f + __expf(-(g.w + bb.w))));
    ((float4*)g_gated)[i] = g;
}

// ---------------------------------------------------------------------------
// tf32 GEMM, 3-stage cp.async, ldmatrix fragment loads.  (unchanged)
// ---------------------------------------------------------------------------
#define GA 4608
#define GB 4608
#define GSTAGES 3
#define GEMM_SMEM_BYTES (GSTAGES * (GA + GB) * 4)

template<int MODE>
__global__ void __launch_bounds__(256, 2) tgemm_kernel(
    const float* __restrict__ A, const float* __restrict__ Wt,
    int K, int NN, const float* __restrict__ bg, float* __restrict__ out)
{
    extern __shared__ unsigned smu[];

    const int tid  = threadIdx.x;
    const int wid  = tid >> 5;
    const int lane = tid & 31;
    const int lr   = lane >> 2;
    const int lc   = lane & 3;
    const int wm   = wid >> 2;
    const int wn   = wid & 3;
    const int row0 = blockIdx.y * 128;
    const int col0 = blockIdx.x * 128;

    const int ar = tid >> 3, ac = (tid & 7) * 4;

    const int arow_l = ((lane >> 3) & 1) * 8 + (lane & 7);
    const int akof_l = ((lane >> 4) & 1) * 4;
    const int brow_l = ((lane >> 4) & 1) * 8 + (lane & 7);
    const int bkof_l = ((lane >> 3) & 1) * 4;
    const unsigned sbase = sptr(smu);
    const unsigned aOff = ((wm * 64 + arow_l) * 36 + akof_l) * 4;
    const unsigned bOff = (GA + (wn * 32 + brow_l) * 36 + bkof_l) * 4;

    float acc[4][4][4];
    #pragma unroll
    for (int mf = 0; mf < 4; mf++)
        #pragma unroll
        for (int nf = 0; nf < 4; nf++)
            #pragma unroll
            for (int e = 0; e < 4; e++) acc[mf][nf][e] = 0.f;

    auto loadChunk = [&](int k0, int buf) {
        unsigned* Ad = smu + buf * (GA + GB);
        unsigned* Bd = Ad + GA;
        #pragma unroll
        for (int it = 0; it < 4; it++) {
            const int r = ar + it * 32;
            CP16(sptr(&Ad[r * 36 + ac]),
                 &A[(size_t)(row0 + r) * K + k0 + ac]);
        }
        #pragma unroll
        for (int it = 0; it < 4; it++) {
            const int r = ar + it * 32;
            CP16(sptr(&Bd[r * 36 + ac]),
                 &Wt[(size_t)(col0 + r) * K + k0 + ac]);
        }
        CP_COMMIT();
    };

    const int nch = K >> 5;
    loadChunk(0, 0);
    loadChunk(32, 1);

    int buf = 0;
    for (int ch = 0; ch < nch; ch++) {
        if (ch + 1 < nch) { CP_WAIT(1); } else { CP_WAIT(0); }
        __syncthreads();
        if (ch + 2 < nch)
            loadChunk((ch + 2) * 32, (buf + 2) % GSTAGES);

        const unsigned cbase = sbase + buf * ((GA + GB) * 4);
        #pragma unroll
        for (int ks = 0; ks < 4; ks++) {
            unsigned a[4][4], b[4][2];
            #pragma unroll
            for (int mf = 0; mf < 4; mf++)
                LDSM4(a[mf][0], a[mf][1], a[mf][2], a[mf][3],
                      cbase + aOff + mf * (16*36*4) + ks * 32);
            #pragma unroll
            for (int p = 0; p < 2; p++)
                LDSM4(b[2*p][0], b[2*p][1], b[2*p+1][0], b[2*p+1][1],
                      cbase + bOff + p * (16*36*4) + ks * 32);
            #pragma unroll
            for (int mf = 0; mf < 4; mf++)
                #pragma unroll
                for (int nf = 0; nf < 4; nf++)
                    mma8(acc[mf][nf], a[mf], b[nf]);
        }
        buf = (buf + 1) % GSTAGES;
    }

    // Epilogue
    #pragma unroll
    for (int mf = 0; mf < 4; mf++) {
        #pragma unroll
        for (int hf = 0; hf < 2; hf++) {
            const int m  = row0 + wm * 64 + mf * 16 + lr + hf * 8;
            const int bb = m >> 11;
            const int ii = m & 2047;
            #pragma unroll
            for (int nf = 0; nf < 4; nf++) {
                const int col = col0 + wn * 32 + nf * 8 + 2 * lc;
                float2 v = make_float2(acc[mf][nf][hf * 2], acc[mf][nf][hf * 2 + 1]);
                if (MODE == 0) {
                    if (col < DI_) {
                        v.x = f2tff(v.x * QSCALE_); v.y = f2tff(v.y * QSCALE_);
                        const int hh = col >> 6, dd = col & 63;
                        *(float2*)&g_q[(((size_t)(bb * H_ + hh)) * N_ + ii) * DH_ + dd] = v;
                    } else if (col < 2 * DI_) {
                        v.x = f2tff(v.x); v.y = f2tff(v.y);
                        const int c = col - DI_;
                        const int hh = c >> 6, dd = c & 63;
                        *(float2*)&g_k[(((size_t)(bb * H_ + hh)) * N_ + ii) * DH_ + dd] = v;
                    } else {
                        const int c = col - 2 * DI_;
                        const int hh = c >> 6, dd = c & 63;
                        float* vb = &g_v[(((size_t)(bb * H_ + hh)) * DH_ + dd) * N_ + ii];
                        vb[0]  = f2tff(v.x);
                        vb[N_] = f2tff(v.y);
                    }
                } else if (MODE == 2) {
                    *(float2*)&g_gated[(size_t)m * DI_ + col] = v;
                } else {
                    *(float2*)&out[(size_t)m * D_ + col] = v;
                }
            }
        }
    }
}

// ---------------------------------------------------------------------------
// Flash attention, tf32 + ldmatrix, base-2 softmax.
// NEW: 4(m)x2(n) warp tiling. Warp (wm,wn) owns 32 q-rows x 32 j-cols.
// K/V LDSM redundancy 8x -> 4x. Softmax max/sum combined across the warp
// pair (wm,0)/(wm,1) via smem + named barrier (id 1+wm, 64 threads).
// Both warps compute identical mi/li state for their shared rows.
// ---------------------------------------------------------------------------
#define AQ (128 * 68)
#define AK (64 * 68)
#define AV (64 * 68)
#define AP (128 * 68)
#define ARED (2 * 128)            // redM[2][128]
#define ATT_SMEM_BYTES ((AQ + AK + AV + AP + 2 * ARED) * 4)

__global__ void __launch_bounds__(256, 2) fattn_kernel(
    const float* __restrict__ bias, const int* __restrict__ mask)
{
    extern __shared__ unsigned sm[];
    unsigned* Qs = sm;                    // [q][d]  stride 68
    unsigned* Ks = Qs + AQ;               // [j][d]  stride 68
    unsigned* Vs = Ks + AK;               // [d][j]  stride 68 (transposed V)
    unsigned* Ps = Vs + AV;               // [q][j]  stride 68
    float* redM  = (float*)(Ps + AP);     // [2][128] partial max
    float* redS  = redM + ARED;           // [2][128] partial sum

    const int tid  = threadIdx.x;
    const int wid  = tid >> 5;
    const int lane = tid & 31;
    const int lr   = lane >> 2;
    const int lc   = lane & 3;
    const int wm   = wid >> 1;            // 0..3 -> q rows 32*wm
    const int wn   = wid & 1;             // 0..1 -> j cols 32*wn
    const int bh   = blockIdx.y;
    const int b    = bh >> 4;
    const int h    = bh & 15;
    const int i0   = blockIdx.x * 128;
    const int q0   = 32 * wm;

    const unsigned* qbase = (const unsigned*)(g_q + ((size_t)bh * N_ + i0) * DH_);
    const float* kbase = g_k + (size_t)bh * N_ * DH_;
    const float* vbase = g_v + (size_t)bh * DH_ * N_;
    const float* bpp = bias + ((size_t)bh * N_ + i0 + q0 + lr) * N_;
    const int* mbase = mask + (size_t)b * N_;

    const int lrow = tid >> 2;
    const int lcol = (tid & 3) * 4;

    const int arow_l = ((lane >> 3) & 1) * 8 + (lane & 7);
    const int akof_l = ((lane >> 4) & 1) * 4;
    const int brow_l = ((lane >> 4) & 1) * 8 + (lane & 7);
    const int bkof_l = ((lane >> 3) & 1) * 4;
    const unsigned qAddr = sptr(Qs) + ((q0 + arow_l) * 68 + akof_l) * 4;
    const unsigned kAddr = sptr(Ks) + ((32 * wn + brow_l) * 68 + bkof_l) * 4;
    const unsigned vAddr = sptr(Vs) + ((32 * wn + brow_l) * 68 + bkof_l) * 4;
    const unsigned pAddr = sptr(Ps) + ((q0 + arow_l) * 68 + akof_l) * 4;

    // Prologue: K(0) async; Q tile raw copy
    #pragma unroll
    for (int it = 0; it < 4; it++) {
        const int c4 = lcol + it * 16;
        CP16(sptr(&Ks[lrow * 68 + c4]), &kbase[(size_t)lrow * DH_ + c4]);
    }
    CP_COMMIT();

    #pragma unroll
    for (int it = 0; it < 8; it++) {
        const int i = tid + it * 256;
        const int r = i >> 4, c4 = (i & 15) * 4;
        *(uint4*)&Qs[r * 68 + c4] = *(const uint4*)&qbase[r * DH_ + c4];
    }

    float S[2][4][4], O[2][4][4];
    float mi[2][2], li[2][2];
    #pragma unroll
    for (int mf = 0; mf < 2; mf++) {
        mi[mf][0] = mi[mf][1] = -1e30f;
        li[mf][0] = li[mf][1] = 0.f;
        #pragma unroll
        for (int nf = 0; nf < 4; nf++)
            O[mf][nf][0] = O[mf][nf][1] = O[mf][nf][2] = O[mf][nf][3] = 0.f;
    }

    const int NT = N_ / 64;
    for (int t = 0; t < NT; t++) {
        const int j0 = t * 64;
        CP_WAIT(0);
        __syncthreads();   // K(t) visible; ALL warps done with prior Vs/Ps

        // Issue V(t)
        #pragma unroll
        for (int it = 0; it < 4; it++) {
            const int c4 = lcol + it * 16;
            CP16(sptr(&Vs[lrow * 68 + c4]), &vbase[(size_t)lrow * N_ + j0 + c4]);
        }
        CP_COMMIT();

        // Bias*log2e + mask preload for this warp's 32x32 S block
        float2 bR[2][2][4];
        #pragma unroll
        for (int nf = 0; nf < 4; nf++) {
            const int jc = j0 + 32 * wn + nf * 8 + 2 * lc;
            int2 mv = *(const int2*)&mbase[jc];
            const float mx = mv.x ? 0.f : -1e30f;
            const float my = mv.y ? 0.f : -1e30f;
            #pragma unroll
            for (int mf = 0; mf < 2; mf++)
                #pragma unroll
                for (int hf = 0; hf < 2; hf++) {
                    float2 tv = *(const float2*)&bpp[(size_t)(16*mf + 8*hf) * N_ + jc];
                    bR[mf][hf][nf].x = fmaf(tv.x, LOG2E_, mx);
                    bR[mf][hf][nf].y = fmaf(tv.y, LOG2E_, my);
                }
        }

        // S = Q @ K^T  (32 q x 32 j per warp)
        #pragma unroll
        for (int mf = 0; mf < 2; mf++)
            #pragma unroll
            for (int nf = 0; nf < 4; nf++)
                S[mf][nf][0] = S[mf][nf][1] = S[mf][nf][2] = S[mf][nf][3] = 0.f;
        #pragma unroll
        for (int ks = 0; ks < 8; ks++) {
            unsigned a[2][4];
            LDSM4(a[0][0], a[0][1], a[0][2], a[0][3], qAddr + ks * 32);
            LDSM4(a[1][0], a[1][1], a[1][2], a[1][3], qAddr + 16*68*4 + ks * 32);
            #pragma unroll
            for (int p = 0; p < 2; p++) {
                unsigned bf[4];
                LDSM4(bf[0], bf[1], bf[2], bf[3],
                      kAddr + p * (16*68*4) + ks * 32);
                #pragma unroll
                for (int mf = 0; mf < 2; mf++) {
                    mma8(S[mf][2*p],     a[mf], &bf[0]);
                    mma8(S[mf][2*p + 1], a[mf], &bf[2]);
                }
            }
        }

        __syncthreads();   // all warps done reading Ks
        if (t + 1 < NT) {
            #pragma unroll
            for (int it = 0; it < 4; it++) {
                const int c4 = lcol + it * 16;
                CP16(sptr(&Ks[lrow * 68 + c4]),
                     &kbase[(size_t)(j0 + 64 + lrow) * DH_ + c4]);
            }
        }
        CP_COMMIT();

        // Add bias+mask; warp-partial row max over this warp's 32 j
        float pmax[2][2];
        #pragma unroll
        for (int mf = 0; mf < 2; mf++) {
            float m0 = -1e30f, m1 = -1e30f;
            #pragma unroll
            for (int nf = 0; nf < 4; nf++) {
                S[mf][nf][0] += bR[mf][0][nf].x;
                S[mf][nf][1] += bR[mf][0][nf].y;
                S[mf][nf][2] += bR[mf][1][nf].x;
                S[mf][nf][3] += bR[mf][1][nf].y;
                m0 = fmaxf(m0, fmaxf(S[mf][nf][0], S[mf][nf][1]));
                m1 = fmaxf(m1, fmaxf(S[mf][nf][2], S[mf][nf][3]));
            }
            m0 = fmaxf(m0, __shfl_xor_sync(~0u, m0, 1));
            m0 = fmaxf(m0, __shfl_xor_sync(~0u, m0, 2));
            m1 = fmaxf(m1, __shfl_xor_sync(~0u, m1, 1));
            m1 = fmaxf(m1, __shfl_xor_sync(~0u, m1, 2));
            pmax[mf][0] = m0; pmax[mf][1] = m1;
        }
        // publish partial max
        if (lc == 0) {
            #pragma unroll
            for (int mf = 0; mf < 2; mf++) {
                redM[wn * 128 + q0 + 16*mf + lr]     = pmax[mf][0];
                redM[wn * 128 + q0 + 16*mf + 8 + lr] = pmax[mf][1];
            }
        }
        PAIR_BAR(1 + wm);
        // combine with partner, update running max, rescale factors
        float cr[2][2], mn[2][2];
        #pragma unroll
        for (int mf = 0; mf < 2; mf++)
            #pragma unroll
            for (int hf = 0; hf < 2; hf++) {
                const float pm = redM[(wn ^ 1) * 128 + q0 + 16*mf + 8*hf + lr];
                const float cmax = fmaxf(pmax[mf][hf], pm);
                mn[mf][hf] = fmaxf(mi[mf][hf], cmax);
                cr[mf][hf] = ex2f(mi[mf][hf] - mn[mf][hf]);
                mi[mf][hf] = mn[mf][hf];
            }

        // exp, partial sum, rescale O, write P
        float psum[2][2];
        #pragma unroll
        for (int mf = 0; mf < 2; mf++) {
            float s0 = 0.f, s1 = 0.f;
            #pragma unroll
            for (int nf = 0; nf < 4; nf++) {
                S[mf][nf][0] = ex2f(S[mf][nf][0] - mn[mf][0]);
                S[mf][nf][1] = ex2f(S[mf][nf][1] - mn[mf][0]);
                S[mf][nf][2] = ex2f(S[mf][nf][2] - mn[mf][1]);
                S[mf][nf][3] = ex2f(S[mf][nf][3] - mn[mf][1]);
                s0 += S[mf][nf][0] + S[mf][nf][1];
                s1 += S[mf][nf][2] + S[mf][nf][3];
                O[mf][nf][0] *= cr[mf][0]; O[mf][nf][1] *= cr[mf][0];
                O[mf][nf][2] *= cr[mf][1]; O[mf][nf][3] *= cr[mf][1];
                const int jc = 32 * wn + nf * 8 + 2 * lc;
                uint2 u0 = make_uint2(f2tf(S[mf][nf][0]), f2tf(S[mf][nf][1]));
                *(uint2*)&Ps[(q0 + 16*mf + lr) * 68 + jc] = u0;
                uint2 u1 = make_uint2(f2tf(S[mf][nf][2]), f2tf(S[mf][nf][3]));
                *(uint2*)&Ps[(q0 + 16*mf + 8 + lr) * 68 + jc] = u1;
            }
            s0 += __shfl_xor_sync(~0u, s0, 1);
            s0 += __shfl_xor_sync(~0u, s0, 2);
            s1 += __shfl_xor_sync(~0u, s1, 1);
            s1 += __shfl_xor_sync(~0u, s1, 2);
            psum[mf][0] = s0; psum[mf][1] = s1;
        }
        if (lc == 0) {
            #pragma unroll
            for (int mf = 0; mf < 2; mf++) {
                redS[wn * 128 + q0 + 16*mf + lr]     = psum[mf][0];
                redS[wn * 128 + q0 + 16*mf + 8 + lr] = psum[mf][1];
            }
        }
        PAIR_BAR(1 + wm);   // also makes pair's P writes visible
        #pragma unroll
        for (int mf = 0; mf < 2; mf++)
            #pragma unroll
            for (int hf = 0; hf < 2; hf++) {
                const float ps = redS[(wn ^ 1) * 128 + q0 + 16*mf + 8*hf + lr];
                li[mf][hf] = li[mf][hf] * cr[mf][hf] + psum[mf][hf] + ps;
            }

        CP_WAIT(1);        // V(t) done (K(t+1) may stay pending)
        __syncthreads();   // V visible across all threads

        // O += P @ V   (A = P rows [q0,q0+32), B = V^T rows [32wn,32wn+32))
        #pragma unroll
        for (int ks = 0; ks < 8; ks++) {
            unsigned a[2][4];
            LDSM4(a[0][0], a[0][1], a[0][2], a[0][3], pAddr + ks * 32);
            LDSM4(a[1][0], a[1][1], a[1][2], a[1][3], pAddr + 16*68*4 + ks * 32);
            #pragma unroll
            for (int p = 0; p < 2; p++) {
                unsigned bf[4];
                LDSM4(bf[0], bf[1], bf[2], bf[3],
                      vAddr + p * (16*68*4) + ks * 32);
                #pragma unroll
                for (int mf = 0; mf < 2; mf++) {
                    mma8(O[mf][2*p],     a[mf], &bf[0]);
                    mma8(O[mf][2*p + 1], a[mf], &bf[2]);
                }
            }
        }
    }

    // Normalize + write token-major [b, i, h*64 + d]
    #pragma unroll
    for (int mf = 0; mf < 2; mf++)
        #pragma unroll
        for (int hf = 0; hf < 2; hf++) {
            const float inv = 1.f / li[mf][hf];
            const size_t row = (size_t)b * N_ + i0 + q0 + 16*mf + 8*hf + lr;
            #pragma unroll
            for (int nf = 0; nf < 4; nf++) {
                const int dd = 32 * wn + nf * 8 + 2 * lc;
                float2 v = make_float2(O[mf][nf][hf*2] * inv,
                                       O[mf][nf][hf*2 + 1] * inv);
                *(float2*)&g_att[row * DI_ + h * DH_ + dd] = v;
            }
        }
}

// ---------------------------------------------------------------------------
extern "C" void kernel_launch(void* const* d_in, const int* in_sizes, int n_in,
                              void* d_out, int out_size)
{
    const float* seq  = (const float*)d_in[0];
    const int*   mask = (const int*)d_in[1];
    const float* bias = (const float*)d_in[2];
    const float* Wq   = (const float*)d_in[3];
    const float* Wkv  = (const float*)d_in[4];
    const float* Wo   = (const float*)d_in[5];
    const float* Wg   = (const float*)d_in[6];
    const float* bg   = (const float*)d_in[7];
    float* out = (float*)d_out;

    static cudaStream_t s1 = nullptr;
    static cudaEvent_t evPrep = nullptr, evGate = nullptr;
    if (s1 == nullptr) {
        cudaStreamCreateWithFlags(&s1, cudaStreamNonBlocking);
        cudaEventCreateWithFlags(&evPrep, cudaEventDisableTiming);
        cudaEventCreateWithFlags(&evGate, cudaEventDisableTiming);
        cudaFuncSetAttribute(tgemm_kernel<0>,
            cudaFuncAttributeMaxDynamicSharedMemorySize, GEMM_SMEM_BYTES);
        cudaFuncSetAttribute(tgemm_kernel<2>,
            cudaFuncAttributeMaxDynamicSharedMemorySize, GEMM_SMEM_BYTES);
        cudaFuncSetAttribute(tgemm_kernel<3>,
            cudaFuncAttributeMaxDynamicSharedMemorySize, GEMM_SMEM_BYTES);
        cudaFuncSetAttribute(fattn_kernel,
            cudaFuncAttributeMaxDynamicSharedMemorySize, ATT_SMEM_BYTES);
    }

    float *p_seq, *p_wqkv, *p_wg, *p_wo, *p_gated;
    cudaGetSymbolAddress((void**)&p_seq,   g_seq);
    cudaGetSymbolAddress((void**)&p_wqkv,  g_wqkv);
    cudaGetSymbolAddress((void**)&p_wg,    g_wg);
    cudaGetSymbolAddress((void**)&p_wo,    g_wo);
    cudaGetSymbolAddress((void**)&p_gated, g_gated);

    // Prepass (main stream)
    prep_seq_kernel<<<(B_*N_*D_/4 + 255) / 256, 256>>>((const float4*)seq);
    prep_wT_kernel<<<5120, 256>>>(Wq, Wkv, Wg, Wo);
    cudaEventRecord(evPrep, 0);

    // Main stream: QKV projection -> attention
    tgemm_kernel<0><<<dim3(3 * DI_ / 128, (B_ * N_) / 128), 256, GEMM_SMEM_BYTES>>>(
        p_seq, p_wqkv, D_, 3 * DI_, nullptr, nullptr);
    fattn_kernel<<<dim3(N_ / 128, B_ * H_), 256, ATT_SMEM_BYTES>>>(bias, mask);

    // Side stream: gate GEMM overlapped with QKV + attention
    cudaStreamWaitEvent(s1, evPrep, 0);
    tgemm_kernel<2><<<dim3(DI_ / 128, (B_ * N_) / 128), 256, GEMM_SMEM_BYTES, s1>>>(
        p_seq, p_wg, D_, DI_, nullptr, nullptr);
    cudaEventRecord(evGate, s1);

    // Join: gating, then output projection
    cudaStreamWaitEvent(0, evGate, 0);
    gating_kernel<<<(B_*N_*DI_/4 + 255) / 256, 256>>>(bg);
    tgemm_kernel<3><<<dim3(D_ / 128, (B_ * N_) / 128), 256, GEMM_SMEM_BYTES>>>(
        p_gated, p_wo, DI_, D_, nullptr, out);
}